// round 5
// baseline (speedup 1.0000x reference)
#include <cuda_runtime.h>
#include <cstdint>

#define DIM   1024
#define FEAT  4096
#define NQ    64
#define NB    8
#define KVR   (NB*(FEAT+NQ))   // 33280 rows of concat(LN(features), LN(latents))
#define LROWS (NB*NQ)          // 512

// Scratch (allocation-free rule: __device__ globals)
__device__ float g_kv[(size_t)KVR*DIM];     // normalized concat input
__device__ float g_k [(size_t)KVR*DIM];     // K projection
__device__ float g_v [(size_t)KVR*DIM];     // V projection
__device__ float g_q [(size_t)LROWS*DIM];   // Q projection (pre-scaled)
__device__ float g_at[(size_t)LROWS*DIM];   // attention output [B,Q,inner]

// ---------------- helpers ----------------
__device__ __forceinline__ unsigned f2t(float x){
    unsigned u; asm("cvt.rna.tf32.f32 %0, %1;" : "=r"(u) : "f"(x)); return u;
}
__device__ __forceinline__ float f2tf(float x){ return __uint_as_float(f2t(x)); }

__device__ __forceinline__ void mma8(float* c, const unsigned* a, const unsigned* b){
    asm volatile(
      "mma.sync.aligned.m16n8k8.row.col.f32.tf32.tf32.f32 "
      "{%0,%1,%2,%3},{%4,%5,%6,%7},{%8,%9},{%0,%1,%2,%3};"
      : "+f"(c[0]), "+f"(c[1]), "+f"(c[2]), "+f"(c[3])
      : "r"(a[0]), "r"(a[1]), "r"(a[2]), "r"(a[3]), "r"(b[0]), "r"(b[1]));
}

// ---------------- LayerNorm (features + latents -> g_kv) ----------------
__global__ __launch_bounds__(256) void ln_kernel(
    const float* __restrict__ feat, const float* __restrict__ lat,
    const float* __restrict__ mw, const float* __restrict__ mb,
    const float* __restrict__ lw, const float* __restrict__ lb)
{
    const int row = blockIdx.x;           // 0..KVR-1
    const int b = row / (FEAT+NQ);
    const int i = row - b*(FEAT+NQ);
    const float *src, *w, *bias;
    if (i < FEAT){ src = feat + (size_t)(b*FEAT + i)*DIM; w = mw; bias = mb; }
    else         { src = lat  + (size_t)(b*NQ + (i-FEAT))*DIM; w = lw; bias = lb; }

    const int tid = threadIdx.x;
    float4 x = ((const float4*)src)[tid];
    float s  = x.x + x.y + x.z + x.w;
    float sq = x.x*x.x + x.y*x.y + x.z*x.z + x.w*x.w;

    __shared__ float red[16];
    #pragma unroll
    for (int o = 16; o > 0; o >>= 1){
        s  += __shfl_xor_sync(0xffffffffu, s, o);
        sq += __shfl_xor_sync(0xffffffffu, sq, o);
    }
    const int wid = tid >> 5, lane = tid & 31;
    if (lane == 0){ red[wid] = s; red[8+wid] = sq; }
    __syncthreads();
    if (wid == 0){
        float ts = (lane < 8) ? red[lane]   : 0.f;
        float tq = (lane < 8) ? red[8+lane] : 0.f;
        #pragma unroll
        for (int o = 4; o > 0; o >>= 1){
            ts += __shfl_xor_sync(0xffffffffu, ts, o);
            tq += __shfl_xor_sync(0xffffffffu, tq, o);
        }
        if (lane == 0){ red[0] = ts; red[1] = tq; }
    }
    __syncthreads();
    const float mu   = red[0] * (1.f/DIM);
    const float var  = red[1] * (1.f/DIM) - mu*mu;
    const float rstd = rsqrtf(var + 1e-5f);

    float4 wv = ((const float4*)w)[tid];
    float4 bv = ((const float4*)bias)[tid];
    float4 y;
    y.x = (x.x - mu)*rstd*wv.x + bv.x;
    y.y = (x.y - mu)*rstd*wv.y + bv.y;
    y.z = (x.z - mu)*rstd*wv.z + bv.z;
    y.w = (x.w - mu)*rstd*wv.w + bv.w;
    ((float4*)(g_kv + (size_t)row*DIM))[tid] = y;
}

// ---------------- tf32 GEMM: C[M,1024] = alpha * A[M,1024] @ B[1024,1024] ----------------
// Block tile 128x128, K-tile 16, 256 threads (8 warps: 4 in M x 2 in N).
// qmode: A rows remapped to the latent rows of g_kv.
__global__ __launch_bounds__(256) void gemm_tf32(
    const float* __restrict__ A, const float* __restrict__ B,
    float* __restrict__ C, int qmode, float alpha)
{
    __shared__ float As[128][17];
    __shared__ float Bs[16][132];

    const int tid  = threadIdx.x;
    const int lane = tid & 31, wid = tid >> 5;
    const int wm = wid & 3, wn = wid >> 2;
    const int g  = lane >> 2, tg = lane & 3;
    const int row0 = blockIdx.y * 128;
    const int col0 = blockIdx.x * 128;

    float acc[2][8][4];
    #pragma unroll
    for (int mi = 0; mi < 2; ++mi)
      #pragma unroll
      for (int ni = 0; ni < 8; ++ni)
        #pragma unroll
        for (int r = 0; r < 4; ++r) acc[mi][ni][r] = 0.f;

    for (int kt = 0; kt < DIM/16; ++kt){
        #pragma unroll
        for (int i = 0; i < 2; ++i){               // A tile: 128x16
            int idx = tid + i*256;
            int r = idx >> 2, c4 = (idx & 3) << 2;
            int grow = row0 + r;
            if (qmode) grow = (grow >> 6)*(FEAT+NQ) + FEAT + (grow & 63);
            const float4 v = *(const float4*)(A + (size_t)grow*DIM + kt*16 + c4);
            As[r][c4+0] = f2tf(v.x); As[r][c4+1] = f2tf(v.y);
            As[r][c4+2] = f2tf(v.z); As[r][c4+3] = f2tf(v.w);
        }
        #pragma unroll
        for (int i = 0; i < 2; ++i){               // B tile: 16x128
            int idx = tid + i*256;
            int kk = idx >> 5, n4 = (idx & 31) << 2;
            const float4 v = *(const float4*)(B + (size_t)(kt*16+kk)*DIM + col0 + n4);
            Bs[kk][n4+0] = f2tf(v.x); Bs[kk][n4+1] = f2tf(v.y);
            Bs[kk][n4+2] = f2tf(v.z); Bs[kk][n4+3] = f2tf(v.w);
        }
        __syncthreads();

        #pragma unroll
        for (int ks = 0; ks < 2; ++ks){
            const int k0 = ks*8;
            unsigned a[2][4], bf[8][2];
            #pragma unroll
            for (int mi = 0; mi < 2; ++mi){
                int r = wm*32 + mi*16;
                a[mi][0] = __float_as_uint(As[r+g  ][k0+tg  ]);
                a[mi][1] = __float_as_uint(As[r+8+g][k0+tg  ]);
                a[mi][2] = __float_as_uint(As[r+g  ][k0+tg+4]);
                a[mi][3] = __float_as_uint(As[r+8+g][k0+tg+4]);
            }
            #pragma unroll
            for (int ni = 0; ni < 8; ++ni){
                int n = wn*64 + ni*8 + g;
                bf[ni][0] = __float_as_uint(Bs[k0+tg  ][n]);
                bf[ni][1] = __float_as_uint(Bs[k0+tg+4][n]);
            }
            #pragma unroll
            for (int mi = 0; mi < 2; ++mi)
              #pragma unroll
              for (int ni = 0; ni < 8; ++ni)
                mma8(acc[mi][ni], a[mi], bf[ni]);
        }
        __syncthreads();
    }

    #pragma unroll
    for (int mi = 0; mi < 2; ++mi){
        const int r0 = row0 + wm*32 + mi*16 + g;
        #pragma unroll
        for (int ni = 0; ni < 8; ++ni){
            const int cc = col0 + wn*64 + ni*8 + tg*2;
            C[(size_t)r0*DIM + cc]       = alpha*acc[mi][ni][0];
            C[(size_t)r0*DIM + cc+1]     = alpha*acc[mi][ni][1];
            C[(size_t)(r0+8)*DIM + cc]   = alpha*acc[mi][ni][2];
            C[(size_t)(r0+8)*DIM + cc+1] = alpha*acc[mi][ni][3];
        }
    }
}

// ---------------- fused flash attention: one block per (b,h) ----------------
// 256 threads = 8 warps: 4 in M(q, 16 each) x 2 in N(32 each, 4 n-atoms).
__global__ __launch_bounds__(256) void attn_kernel(
    const int* __restrict__ mask, float* __restrict__ gattn)
{
    __shared__ float Ks[64][68];   // K tile, then overlaid with S/P
    __shared__ float Vs[64][68];
    __shared__ float madd[64];
    __shared__ float alpha_s[64], m_s[64], l_s[64];

    const int h = blockIdx.x, b = blockIdx.y;
    const int tid = threadIdx.x, lane = tid & 31, wid = tid >> 5;
    const int wm = wid & 3, wn = wid >> 2;
    const int g = lane >> 2, tg = lane & 3;

    // Q fragments, register-resident (already scaled by dh^-0.5 in the GEMM)
    unsigned qf[8][4];
    {
        const float* qp = g_q + (size_t)(b*NQ + wm*16)*DIM + h*64;
        #pragma unroll
        for (int ks = 0; ks < 8; ++ks){
            qf[ks][0] = f2t(qp[(size_t)(g  )*DIM + ks*8+tg  ]);
            qf[ks][1] = f2t(qp[(size_t)(g+8)*DIM + ks*8+tg  ]);
            qf[ks][2] = f2t(qp[(size_t)(g  )*DIM + ks*8+tg+4]);
            qf[ks][3] = f2t(qp[(size_t)(g+8)*DIM + ks*8+tg+4]);
        }
    }
    float o[4][4];
    #pragma unroll
    for (int ni = 0; ni < 4; ++ni)
      #pragma unroll
      for (int r = 0; r < 4; ++r) o[ni][r] = 0.f;

    if (tid < 64){ m_s[tid] = -1e30f; l_s[tid] = 0.f; }
    __syncthreads();

    for (int c = 0; c < 65; ++c){
        const size_t rbase = (size_t)(b*(FEAT+NQ) + c*64);
        #pragma unroll
        for (int i = 0; i < 4; ++i){          // load K, V chunk 64x64 each
            int idx = tid + i*256;
            int r = idx >> 4, c4 = (idx & 15) << 2;
            const float4 kk = *(const float4*)(g_k + (rbase+r)*DIM + h*64 + c4);
            Ks[r][c4+0]=f2tf(kk.x); Ks[r][c4+1]=f2tf(kk.y); Ks[r][c4+2]=f2tf(kk.z); Ks[r][c4+3]=f2tf(kk.w);
            const float4 vv = *(const float4*)(g_v + (rbase+r)*DIM + h*64 + c4);
            Vs[r][c4+0]=f2tf(vv.x); Vs[r][c4+1]=f2tf(vv.y); Vs[r][c4+2]=f2tf(vv.z); Vs[r][c4+3]=f2tf(vv.w);
        }
        if (tid < 64)
            madd[tid] = (c < 64) ? (mask[b*FEAT + c*64 + tid] ? 0.f : -1e30f) : 0.f;
        __syncthreads();

        // S = Q @ K^T
        float s[4][4];
        #pragma unroll
        for (int ni = 0; ni < 4; ++ni)
          #pragma unroll
          for (int r = 0; r < 4; ++r) s[ni][r] = 0.f;
        #pragma unroll
        for (int ks = 0; ks < 8; ++ks){
            unsigned bf[4][2];
            #pragma unroll
            for (int ni = 0; ni < 4; ++ni){
                int n = wn*32 + ni*8 + g;
                bf[ni][0] = __float_as_uint(Ks[n][ks*8+tg  ]);
                bf[ni][1] = __float_as_uint(Ks[n][ks*8+tg+4]);
            }
            #pragma unroll
            for (int ni = 0; ni < 4; ++ni) mma8(s[ni], qf[ks], bf[ni]);
        }
        __syncthreads();

        // write S + mask into Ks (overlay)
        {
            const int r0 = wm*16 + g;
            #pragma unroll
            for (int ni = 0; ni < 4; ++ni){
                int cc = wn*32 + ni*8 + tg*2;
                Ks[r0  ][cc]   = s[ni][0] + madd[cc];
                Ks[r0  ][cc+1] = s[ni][1] + madd[cc+1];
                Ks[r0+8][cc]   = s[ni][2] + madd[cc];
                Ks[r0+8][cc+1] = s[ni][3] + madd[cc+1];
            }
        }
        __syncthreads();

        // online softmax: 4 threads per q row
        {
            const int q = tid >> 2, part = tid & 3;
            float pm = -1e30f;
            #pragma unroll
            for (int j = 0; j < 16; ++j) pm = fmaxf(pm, Ks[q][part*16+j]);
            pm = fmaxf(pm, __shfl_xor_sync(0xffffffffu, pm, 1));
            pm = fmaxf(pm, __shfl_xor_sync(0xffffffffu, pm, 2));
            const float mold = m_s[q];
            const float mnew = fmaxf(mold, pm);
            float psum = 0.f;
            #pragma unroll
            for (int j = 0; j < 16; ++j){
                float sv = Ks[q][part*16+j];
                float p  = (sv > -1e29f) ? __expf(sv - mnew) : 0.f;
                Ks[q][part*16+j] = f2tf(p);
                psum += p;
            }
            psum += __shfl_xor_sync(0xffffffffu, psum, 1);
            psum += __shfl_xor_sync(0xffffffffu, psum, 2);
            if (part == 0){
                float al = __expf(mold - mnew);
                alpha_s[q] = al;
                m_s[q]     = mnew;
                l_s[q]     = l_s[q]*al + psum;
            }
        }
        __syncthreads();

        // rescale O, then O += P @ V
        {
            const float al0 = alpha_s[wm*16 + g];
            const float al1 = alpha_s[wm*16 + 8 + g];
            #pragma unroll
            for (int ni = 0; ni < 4; ++ni){
                o[ni][0]*=al0; o[ni][1]*=al0; o[ni][2]*=al1; o[ni][3]*=al1;
            }
            #pragma unroll
            for (int ks = 0; ks < 8; ++ks){
                unsigned pa[4];
                const int r0 = wm*16;
                pa[0] = __float_as_uint(Ks[r0+g  ][ks*8+tg  ]);
                pa[1] = __float_as_uint(Ks[r0+8+g][ks*8+tg  ]);
                pa[2] = __float_as_uint(Ks[r0+g  ][ks*8+tg+4]);
                pa[3] = __float_as_uint(Ks[r0+8+g][ks*8+tg+4]);
                unsigned bf[4][2];
                #pragma unroll
                for (int ni = 0; ni < 4; ++ni){
                    int n = wn*32 + ni*8 + g;
                    bf[ni][0] = __float_as_uint(Vs[ks*8+tg  ][n]);
                    bf[ni][1] = __float_as_uint(Vs[ks*8+tg+4][n]);
                }
                #pragma unroll
                for (int ni = 0; ni < 4; ++ni) mma8(o[ni], pa, bf[ni]);
            }
        }
        __syncthreads();
    }

    // epilogue: divide by l, write [B,Q,inner]
    {
        const float li0 = 1.f / l_s[wm*16 + g];
        const float li1 = 1.f / l_s[wm*16 + 8 + g];
        const int r0 = b*NQ + wm*16 + g;
        #pragma unroll
        for (int ni = 0; ni < 4; ++ni){
            int cc = h*64 + wn*32 + ni*8 + tg*2;
            gattn[(size_t)r0*DIM + cc]       = o[ni][0]*li0;
            gattn[(size_t)r0*DIM + cc+1]     = o[ni][1]*li0;
            gattn[(size_t)(r0+8)*DIM + cc]   = o[ni][2]*li1;
            gattn[(size_t)(r0+8)*DIM + cc+1] = o[ni][3]*li1;
        }
    }
}

// ---------------- launch ----------------
extern "C" void kernel_launch(void* const* d_in, const int* in_sizes, int n_in,
                              void* d_out, int out_size)
{
    const float* feat = (const float*)d_in[0];
    const float* lat  = (const float*)d_in[1];
    const int*   msk  = (const int*)  d_in[2];
    const float* mw   = (const float*)d_in[3];
    const float* mb   = (const float*)d_in[4];
    const float* lw   = (const float*)d_in[5];
    const float* lb   = (const float*)d_in[6];
    const float* Wq   = (const float*)d_in[7];
    const float* Wk   = (const float*)d_in[8];
    const float* Wv   = (const float*)d_in[9];
    const float* Wo   = (const float*)d_in[10];
    float* out = (float*)d_out;

    float *p_kv, *p_k, *p_v, *p_q, *p_at;
    cudaGetSymbolAddress((void**)&p_kv, g_kv);
    cudaGetSymbolAddress((void**)&p_k,  g_k);
    cudaGetSymbolAddress((void**)&p_v,  g_v);
    cudaGetSymbolAddress((void**)&p_q,  g_q);
    cudaGetSymbolAddress((void**)&p_at, g_at);

    ln_kernel<<<KVR, 256>>>(feat, lat, mw, mb, lw, lb);

    dim3 gbig(8, KVR/128);         // n-fastest: 8 n-blocks share A rows via L2
    gemm_tf32<<<gbig, 256>>>(p_kv, Wk, p_k, 0, 1.0f);
    gemm_tf32<<<gbig, 256>>>(p_kv, Wv, p_v, 0, 1.0f);

    dim3 gsmall(8, LROWS/128);
    gemm_tf32<<<gsmall, 256>>>(p_kv, Wq, p_q, 1, 0.125f);   // dh^-0.5 folded in

    dim3 gattn(16, NB);            // (h, b)
    attn_kernel<<<gattn, 256>>>(msk, p_at);

    gemm_tf32<<<gsmall, 256>>>(p_at, Wo, out, 0, 1.0f);
}

// round 10
// speedup vs baseline: 1.7047x; 1.7047x over previous
#include <cuda_runtime.h>
#include <cstdint>

#define DIM   1024
#define FEAT  4096
#define NQ    64
#define NB    8
#define KVR   (NB*(FEAT+NQ))   // 33280
#define LROWS (NB*NQ)          // 512

#define KT     32              // k-tile (floats)
#define NKT    (DIM/KT)        // 32
#define APAD   36
#define BPAD   132
#define STG_F  (128*APAD + KT*BPAD)   // floats per stage = 8832
#define NSTAGE 3
#define GEMM_SMEM (NSTAGE*STG_F*4)    // 105984 bytes

// Scratch (allocation-free rule: __device__ globals)
__device__ float g_kv[(size_t)KVR*DIM];
__device__ float g_k [(size_t)KVR*DIM];
__device__ float g_v [(size_t)KVR*DIM];
__device__ float g_q [(size_t)LROWS*DIM];
__device__ float g_at[(size_t)LROWS*DIM];
__device__ float g_w [(size_t)4*DIM*DIM];   // tf32-rounded Wk,Wv,Wq,Wo

// ---------------- helpers ----------------
__device__ __forceinline__ unsigned f2t(float x){
    unsigned u; asm("cvt.rna.tf32.f32 %0, %1;" : "=r"(u) : "f"(x)); return u;
}
__device__ __forceinline__ float f2tf(float x){ return __uint_as_float(f2t(x)); }

__device__ __forceinline__ void mma8(float* c, const unsigned* a, const unsigned* b){
    asm volatile(
      "mma.sync.aligned.m16n8k8.row.col.f32.tf32.tf32.f32 "
      "{%0,%1,%2,%3},{%4,%5,%6,%7},{%8,%9},{%0,%1,%2,%3};"
      : "+f"(c[0]), "+f"(c[1]), "+f"(c[2]), "+f"(c[3])
      : "r"(a[0]), "r"(a[1]), "r"(a[2]), "r"(a[3]), "r"(b[0]), "r"(b[1]));
}

__device__ __forceinline__ uint32_t smem_u32(const void* p){
    uint32_t a;
    asm("{.reg .u64 t; cvta.to.shared.u64 t, %1; cvt.u32.u64 %0, t;}" : "=r"(a) : "l"(p));
    return a;
}
__device__ __forceinline__ void cpasync16(uint32_t d, const void* s){
    asm volatile("cp.async.cg.shared.global [%0], [%1], 16;" :: "r"(d), "l"(s));
}
__device__ __forceinline__ void cp_commit(){ asm volatile("cp.async.commit_group;" ::: "memory"); }
__device__ __forceinline__ void cp_wait1(){ asm volatile("cp.async.wait_group 1;" ::: "memory"); }

// ---------------- tf32 weight pre-round ----------------
__global__ __launch_bounds__(256) void round_kernel(const float* __restrict__ s,
                                                    float* __restrict__ d){
    size_t i = ((size_t)blockIdx.x*256 + threadIdx.x)*4;
    float4 v = *(const float4*)(s+i);
    v.x = f2tf(v.x); v.y = f2tf(v.y); v.z = f2tf(v.z); v.w = f2tf(v.w);
    *(float4*)(d+i) = v;
}

// ---------------- LayerNorm (outputs pre-rounded to tf32) ----------------
__global__ __launch_bounds__(256) void ln_kernel(
    const float* __restrict__ feat, const float* __restrict__ lat,
    const float* __restrict__ mw, const float* __restrict__ mb,
    const float* __restrict__ lw, const float* __restrict__ lb)
{
    const int row = blockIdx.x;
    const int b = row / (FEAT+NQ);
    const int i = row - b*(FEAT+NQ);
    const float *src, *w, *bias;
    if (i < FEAT){ src = feat + (size_t)(b*FEAT + i)*DIM; w = mw; bias = mb; }
    else         { src = lat  + (size_t)(b*NQ + (i-FEAT))*DIM; w = lw; bias = lb; }

    const int tid = threadIdx.x;
    float4 x = ((const float4*)src)[tid];
    float s  = x.x + x.y + x.z + x.w;
    float sq = x.x*x.x + x.y*x.y + x.z*x.z + x.w*x.w;

    __shared__ float red[16];
    #pragma unroll
    for (int o = 16; o > 0; o >>= 1){
        s  += __shfl_xor_sync(0xffffffffu, s, o);
        sq += __shfl_xor_sync(0xffffffffu, sq, o);
    }
    const int wid = tid >> 5, lane = tid & 31;
    if (lane == 0){ red[wid] = s; red[8+wid] = sq; }
    __syncthreads();
    if (wid == 0){
        float ts = (lane < 8) ? red[lane]   : 0.f;
        float tq = (lane < 8) ? red[8+lane] : 0.f;
        #pragma unroll
        for (int o = 4; o > 0; o >>= 1){
            ts += __shfl_xor_sync(0xffffffffu, ts, o);
            tq += __shfl_xor_sync(0xffffffffu, tq, o);
        }
        if (lane == 0){ red[0] = ts; red[1] = tq; }
    }
    __syncthreads();
    const float mu   = red[0] * (1.f/DIM);
    const float var  = red[1] * (1.f/DIM) - mu*mu;
    const float rstd = rsqrtf(var + 1e-5f);

    float4 wv = ((const float4*)w)[tid];
    float4 bv = ((const float4*)bias)[tid];
    float4 y;
    y.x = f2tf((x.x - mu)*rstd*wv.x + bv.x);
    y.y = f2tf((x.y - mu)*rstd*wv.y + bv.y);
    y.z = f2tf((x.z - mu)*rstd*wv.z + bv.z);
    y.w = f2tf((x.w - mu)*rstd*wv.w + bv.w);
    ((float4*)(g_kv + (size_t)row*DIM))[tid] = y;
}

// ---------------- pipelined tf32 GEMM: C[M,1024] = alpha * A @ B ----------------
// 128x128 CTA tile, k-tile 32, 3-stage cp.async pipeline, 8 warps = 2(M)x4(N).
// A and B must be pre-rounded to tf32 (raw copies here).
__global__ __launch_bounds__(256) void gemm_mma(
    const float* __restrict__ A, const float* __restrict__ B,
    float* __restrict__ C, int qmode, float alpha)
{
    extern __shared__ float sm[];
    const int tid = threadIdx.x, lane = tid & 31, wid = tid >> 5;
    const int wm = wid & 1, wn = wid >> 1;
    const int g = lane >> 2, tg = lane & 3;
    const int row0 = blockIdx.y * 128, col0 = blockIdx.x * 128;

    const uint32_t sbase = smem_u32(sm);

    // A loader: pass p in 0..3 -> row p*32 + (tid>>3), 16B chunk (tid&7)
    const int ar = tid >> 3, ac = tid & 7;
    const float* asrc[4];
    uint32_t adst[4];
    #pragma unroll
    for (int p = 0; p < 4; ++p){
        int r = p*32 + ar;
        int grow = row0 + r;
        if (qmode) grow = (grow >> 6)*(FEAT+NQ) + FEAT + (grow & 63);
        asrc[p] = A + (size_t)grow*DIM + ac*4;
        adst[p] = sbase + (uint32_t)(r*APAD + ac*4)*4u;
    }
    // B loader: pass p in 0..3 -> k-row p*8 + (tid>>5), 16B chunk (tid&31)
    const int bk = tid >> 5, bc = tid & 31;
    const float* bsrc0 = B + (size_t)bk*DIM + col0 + bc*4;
    const uint32_t bdst0 = sbase + (uint32_t)(128*APAD + bk*BPAD + bc*4)*4u;

    float acc[4][4][4];
    #pragma unroll
    for (int mi = 0; mi < 4; ++mi)
      #pragma unroll
      for (int ni = 0; ni < 4; ++ni)
        #pragma unroll
        for (int r = 0; r < 4; ++r) acc[mi][ni][r] = 0.f;

    // prologue: fill stages 0,1
    #pragma unroll
    for (int pre = 0; pre < 2; ++pre){
        const uint32_t so = (uint32_t)pre*STG_F*4u;
        #pragma unroll
        for (int p = 0; p < 4; ++p) cpasync16(adst[p]+so, asrc[p] + pre*KT);
        #pragma unroll
        for (int p = 0; p < 4; ++p) cpasync16(bdst0+so + (uint32_t)(p*8*BPAD)*4u,
                                              bsrc0 + (size_t)(pre*KT + p*8)*DIM);
        cp_commit();
    }

    for (int kt = 0; kt < NKT; ++kt){
        const int slot = kt % NSTAGE;
        cp_wait1();
        __syncthreads();

        // issue loads for kt+2 into slot (kt+2)%3 (freed at iteration kt-1)
        if (kt + 2 < NKT){
            const int ns = (kt+2) % NSTAGE;
            const uint32_t so = (uint32_t)ns*STG_F*4u;
            #pragma unroll
            for (int p = 0; p < 4; ++p) cpasync16(adst[p]+so, asrc[p] + (kt+2)*KT);
            #pragma unroll
            for (int p = 0; p < 4; ++p) cpasync16(bdst0+so + (uint32_t)(p*8*BPAD)*4u,
                                                  bsrc0 + (size_t)((kt+2)*KT + p*8)*DIM);
        }
        cp_commit();

        const float* as = sm + (size_t)slot*STG_F;
        const float* bs = as + 128*APAD;
        #pragma unroll
        for (int ks = 0; ks < 4; ++ks){
            const int k0 = ks*8;
            unsigned a[4][4], bf[4][2];
            #pragma unroll
            for (int mi = 0; mi < 4; ++mi){
                const float* ap = as + (wm*64 + mi*16 + g)*APAD + k0 + tg;
                a[mi][0] = __float_as_uint(ap[0]);
                a[mi][1] = __float_as_uint(ap[8*APAD]);
                a[mi][2] = __float_as_uint(ap[4]);
                a[mi][3] = __float_as_uint(ap[8*APAD+4]);
            }
            #pragma unroll
            for (int ni = 0; ni < 4; ++ni){
                const float* bp = bs + (k0+tg)*BPAD + wn*32 + ni*8 + g;
                bf[ni][0] = __float_as_uint(bp[0]);
                bf[ni][1] = __float_as_uint(bp[4*BPAD]);
            }
            #pragma unroll
            for (int mi = 0; mi < 4; ++mi)
              #pragma unroll
              for (int ni = 0; ni < 4; ++ni)
                mma8(acc[mi][ni], a[mi], bf[ni]);
        }
    }

    // epilogue
    #pragma unroll
    for (int mi = 0; mi < 4; ++mi){
        #pragma unroll
        for (int r2 = 0; r2 < 2; ++r2){
            const int row = row0 + wm*64 + mi*16 + r2*8 + g;
            float* cp = C + (size_t)row*DIM + col0 + wn*32 + tg*2;
            #pragma unroll
            for (int ni = 0; ni < 4; ++ni){
                float2 v;
                v.x = alpha*acc[mi][ni][r2*2];
                v.y = alpha*acc[mi][ni][r2*2+1];
                *(float2*)(cp + ni*8) = v;
            }
        }
    }
}

// ---------------- fused flash attention (unchanged; passing) ----------------
__global__ __launch_bounds__(256) void attn_kernel(
    const int* __restrict__ mask, float* __restrict__ gattn)
{
    __shared__ float Ks[64][68];
    __shared__ float Vs[64][68];
    __shared__ float madd[64];
    __shared__ float alpha_s[64], m_s[64], l_s[64];

    const int h = blockIdx.x, b = blockIdx.y;
    const int tid = threadIdx.x, lane = tid & 31, wid = tid >> 5;
    const int wm = wid & 3, wn = wid >> 2;
    const int g = lane >> 2, tg = lane & 3;

    unsigned qf[8][4];
    {
        const float* qp = g_q + (size_t)(b*NQ + wm*16)*DIM + h*64;
        #pragma unroll
        for (int ks = 0; ks < 8; ++ks){
            qf[ks][0] = f2t(qp[(size_t)(g  )*DIM + ks*8+tg  ]);
            qf[ks][1] = f2t(qp[(size_t)(g+8)*DIM + ks*8+tg  ]);
            qf[ks][2] = f2t(qp[(size_t)(g  )*DIM + ks*8+tg+4]);
            qf[ks][3] = f2t(qp[(size_t)(g+8)*DIM + ks*8+tg+4]);
        }
    }
    float o[4][4];
    #pragma unroll
    for (int ni = 0; ni < 4; ++ni)
      #pragma unroll
      for (int r = 0; r < 4; ++r) o[ni][r] = 0.f;

    if (tid < 64){ m_s[tid] = -1e30f; l_s[tid] = 0.f; }
    __syncthreads();

    for (int c = 0; c < 65; ++c){
        const size_t rbase = (size_t)(b*(FEAT+NQ) + c*64);
        #pragma unroll
        for (int i = 0; i < 4; ++i){
            int idx = tid + i*256;
            int r = idx >> 4, c4 = (idx & 15) << 2;
            const float4 kk = *(const float4*)(g_k + (rbase+r)*DIM + h*64 + c4);
            Ks[r][c4+0]=f2tf(kk.x); Ks[r][c4+1]=f2tf(kk.y); Ks[r][c4+2]=f2tf(kk.z); Ks[r][c4+3]=f2tf(kk.w);
            const float4 vv = *(const float4*)(g_v + (rbase+r)*DIM + h*64 + c4);
            Vs[r][c4+0]=f2tf(vv.x); Vs[r][c4+1]=f2tf(vv.y); Vs[r][c4+2]=f2tf(vv.z); Vs[r][c4+3]=f2tf(vv.w);
        }
        if (tid < 64)
            madd[tid] = (c < 64) ? (mask[b*FEAT + c*64 + tid] ? 0.f : -1e30f) : 0.f;
        __syncthreads();

        float s[4][4];
        #pragma unroll
        for (int ni = 0; ni < 4; ++ni)
          #pragma unroll
          for (int r = 0; r < 4; ++r) s[ni][r] = 0.f;
        #pragma unroll
        for (int ks = 0; ks < 8; ++ks){
            unsigned bf[4][2];
            #pragma unroll
            for (int ni = 0; ni < 4; ++ni){
                int n = wn*32 + ni*8 + g;
                bf[ni][0] = __float_as_uint(Ks[n][ks*8+tg  ]);
                bf[ni][1] = __float_as_uint(Ks[n][ks*8+tg+4]);
            }
            #pragma unroll
            for (int ni = 0; ni < 4; ++ni) mma8(s[ni], qf[ks], bf[ni]);
        }
        __syncthreads();

        {
            const int r0 = wm*16 + g;
            #pragma unroll
            for (int ni = 0; ni < 4; ++ni){
                int cc = wn*32 + ni*8 + tg*2;
                Ks[r0  ][cc]   = s[ni][0] + madd[cc];
                Ks[r0  ][cc+1] = s[ni][1] + madd[cc+1];
                Ks[r0+8][cc]   = s[ni][2] + madd[cc];
                Ks[r0+8][cc+1] = s[ni][3] + madd[cc+1];
            }
        }
        __syncthreads();

        {
            const int q = tid >> 2, part = tid & 3;
            float pm = -1e30f;
            #pragma unroll
            for (int j = 0; j < 16; ++j) pm = fmaxf(pm, Ks[q][part*16+j]);
            pm = fmaxf(pm, __shfl_xor_sync(0xffffffffu, pm, 1));
            pm = fmaxf(pm, __shfl_xor_sync(0xffffffffu, pm, 2));
            const float mold = m_s[q];
            const float mnew = fmaxf(mold, pm);
            float psum = 0.f;
            #pragma unroll
            for (int j = 0; j < 16; ++j){
                float sv = Ks[q][part*16+j];
                float p  = (sv > -1e29f) ? __expf(sv - mnew) : 0.f;
                Ks[q][part*16+j] = f2tf(p);
                psum += p;
            }
            psum += __shfl_xor_sync(0xffffffffu, psum, 1);
            psum += __shfl_xor_sync(0xffffffffu, psum, 2);
            if (part == 0){
                float al = __expf(mold - mnew);
                alpha_s[q] = al;
                m_s[q]     = mnew;
                l_s[q]     = l_s[q]*al + psum;
            }
        }
        __syncthreads();

        {
            const float al0 = alpha_s[wm*16 + g];
            const float al1 = alpha_s[wm*16 + 8 + g];
            #pragma unroll
            for (int ni = 0; ni < 4; ++ni){
                o[ni][0]*=al0; o[ni][1]*=al0; o[ni][2]*=al1; o[ni][3]*=al1;
            }
            #pragma unroll
            for (int ks = 0; ks < 8; ++ks){
                unsigned pa[4];
                const int r0 = wm*16;
                pa[0] = __float_as_uint(Ks[r0+g  ][ks*8+tg  ]);
                pa[1] = __float_as_uint(Ks[r0+8+g][ks*8+tg  ]);
                pa[2] = __float_as_uint(Ks[r0+g  ][ks*8+tg+4]);
                pa[3] = __float_as_uint(Ks[r0+8+g][ks*8+tg+4]);
                unsigned bf[4][2];
                #pragma unroll
                for (int ni = 0; ni < 4; ++ni){
                    int n = wn*32 + ni*8 + g;
                    bf[ni][0] = __float_as_uint(Vs[ks*8+tg  ][n]);
                    bf[ni][1] = __float_as_uint(Vs[ks*8+tg+4][n]);
                }
                #pragma unroll
                for (int ni = 0; ni < 4; ++ni) mma8(o[ni], pa, bf[ni]);
            }
        }
        __syncthreads();
    }

    // epilogue: divide by l, pre-round to tf32 for the O-projection GEMM
    {
        const float li0 = 1.f / l_s[wm*16 + g];
        const float li1 = 1.f / l_s[wm*16 + 8 + g];
        const int r0 = b*NQ + wm*16 + g;
        #pragma unroll
        for (int ni = 0; ni < 4; ++ni){
            int cc = h*64 + wn*32 + ni*8 + tg*2;
            gattn[(size_t)r0*DIM + cc]       = f2tf(o[ni][0]*li0);
            gattn[(size_t)r0*DIM + cc+1]     = f2tf(o[ni][1]*li0);
            gattn[(size_t)(r0+8)*DIM + cc]   = f2tf(o[ni][2]*li1);
            gattn[(size_t)(r0+8)*DIM + cc+1] = f2tf(o[ni][3]*li1);
        }
    }
}

// ---------------- launch ----------------
extern "C" void kernel_launch(void* const* d_in, const int* in_sizes, int n_in,
                              void* d_out, int out_size)
{
    const float* feat = (const float*)d_in[0];
    const float* lat  = (const float*)d_in[1];
    const int*   msk  = (const int*)  d_in[2];
    const float* mw   = (const float*)d_in[3];
    const float* mb   = (const float*)d_in[4];
    const float* lw   = (const float*)d_in[5];
    const float* lb   = (const float*)d_in[6];
    const float* Wq   = (const float*)d_in[7];
    const float* Wk   = (const float*)d_in[8];
    const float* Wv   = (const float*)d_in[9];
    const float* Wo   = (const float*)d_in[10];
    float* out = (float*)d_out;

    float *p_kv, *p_k, *p_v, *p_q, *p_at, *p_w;
    cudaGetSymbolAddress((void**)&p_kv, g_kv);
    cudaGetSymbolAddress((void**)&p_k,  g_k);
    cudaGetSymbolAddress((void**)&p_v,  g_v);
    cudaGetSymbolAddress((void**)&p_q,  g_q);
    cudaGetSymbolAddress((void**)&p_at, g_at);
    cudaGetSymbolAddress((void**)&p_w,  g_w);

    cudaFuncSetAttribute(gemm_mma, cudaFuncAttributeMaxDynamicSharedMemorySize, GEMM_SMEM);

    const int WB = (DIM*DIM)/1024;   // 1024 blocks per weight
    round_kernel<<<WB, 256>>>(Wk, p_w + 0*(size_t)DIM*DIM);
    round_kernel<<<WB, 256>>>(Wv, p_w + 1*(size_t)DIM*DIM);
    round_kernel<<<WB, 256>>>(Wq, p_w + 2*(size_t)DIM*DIM);
    round_kernel<<<WB, 256>>>(Wo, p_w + 3*(size_t)DIM*DIM);

    ln_kernel<<<KVR, 256>>>(feat, lat, mw, mb, lw, lb);

    dim3 gbig(8, KVR/128);          // x-fastest: 8 n-blocks share A tiles via L2
    gemm_mma<<<gbig, 256, GEMM_SMEM>>>(p_kv, p_w + 0*(size_t)DIM*DIM, p_k, 0, 1.0f);
    gemm_mma<<<gbig, 256, GEMM_SMEM>>>(p_kv, p_w + 1*(size_t)DIM*DIM, p_v, 0, 1.0f);

    dim3 gsmall(8, LROWS/128);
    gemm_mma<<<gsmall, 256, GEMM_SMEM>>>(p_kv, p_w + 2*(size_t)DIM*DIM, p_q, 1, 0.125f);

    dim3 gattn(16, NB);
    attn_kernel<<<gattn, 256>>>(msk, p_at);

    gemm_mma<<<gsmall, 256, GEMM_SMEM>>>(p_at, p_w + 3*(size_t)DIM*DIM, out, 0, 1.0f);
}

// round 11
// speedup vs baseline: 1.9492x; 1.1434x over previous
#include <cuda_runtime.h>
#include <cstdint>

#define DIM   1024
#define FEAT  4096
#define NQ    64
#define NB    8
#define KVR   (NB*(FEAT+NQ))   // 33280
#define LROWS (NB*NQ)          // 512

#define KT     32              // k-tile (floats)
#define NKT    (DIM/KT)        // 32
#define APAD   36
#define BPAD   136             // (8*tg+g) bank pattern -> conflict-free frags
#define NSTAGE 3
#define STG_F   (128*APAD + KT*BPAD)       // 8960  floats / stage (single-B)
#define STGKV_F (128*APAD + 2*KT*BPAD)     // 13312 floats / stage (fused KV)
#define GEMM_SMEM   (NSTAGE*STG_F*4)       // 107520 B
#define GEMMKV_SMEM (NSTAGE*STGKV_F*4)     // 159744 B

#define NSPLIT 2
#define SPLIT_MID 33                       // tiles [0,33) / [33,65)
#define MLSZ (NB*16*64)                    // 8192 (b,h,q) slots per split

// Scratch (allocation-free rule: __device__ globals)
__device__ float g_kv[(size_t)KVR*DIM];
__device__ float g_k [(size_t)KVR*DIM];
__device__ float g_v [(size_t)KVR*DIM];
__device__ float g_q [(size_t)LROWS*DIM];
__device__ float g_at[(size_t)LROWS*DIM];
__device__ float g_w [(size_t)4*DIM*DIM];        // tf32-rounded Wk,Wv,Wq,Wo
__device__ float g_po[(size_t)NSPLIT*LROWS*DIM]; // attention partial numerators
__device__ float g_sm[NSPLIT*MLSZ];              // partial row max
__device__ float g_sl[NSPLIT*MLSZ];              // partial row sum

// ---------------- helpers ----------------
__device__ __forceinline__ unsigned f2t(float x){
    unsigned u; asm("cvt.rna.tf32.f32 %0, %1;" : "=r"(u) : "f"(x)); return u;
}
__device__ __forceinline__ float f2tf(float x){ return __uint_as_float(f2t(x)); }

__device__ __forceinline__ void mma8(float* c, const unsigned* a, const unsigned* b){
    asm volatile(
      "mma.sync.aligned.m16n8k8.row.col.f32.tf32.tf32.f32 "
      "{%0,%1,%2,%3},{%4,%5,%6,%7},{%8,%9},{%0,%1,%2,%3};"
      : "+f"(c[0]), "+f"(c[1]), "+f"(c[2]), "+f"(c[3])
      : "r"(a[0]), "r"(a[1]), "r"(a[2]), "r"(a[3]), "r"(b[0]), "r"(b[1]));
}

__device__ __forceinline__ uint32_t smem_u32(const void* p){
    uint32_t a;
    asm("{.reg .u64 t; cvta.to.shared.u64 t, %1; cvt.u32.u64 %0, t;}" : "=r"(a) : "l"(p));
    return a;
}
__device__ __forceinline__ void cpasync16(uint32_t d, const void* s){
    asm volatile("cp.async.cg.shared.global [%0], [%1], 16;" :: "r"(d), "l"(s));
}
__device__ __forceinline__ void cp_commit(){ asm volatile("cp.async.commit_group;" ::: "memory"); }
__device__ __forceinline__ void cp_wait1(){ asm volatile("cp.async.wait_group 1;" ::: "memory"); }

// ---------------- tf32 weight pre-round (all 4 weights, one launch) ----------------
__global__ __launch_bounds__(256) void round_all(
    const float* __restrict__ s0, const float* __restrict__ s1,
    const float* __restrict__ s2, const float* __restrict__ s3,
    float* __restrict__ d)
{
    const int w = blockIdx.x >> 10;             // 1024 blocks per weight
    const float* s = (w==0) ? s0 : (w==1) ? s1 : (w==2) ? s2 : s3;
    const size_t i = ((size_t)(blockIdx.x & 1023)*256 + threadIdx.x)*4;
    float4 v = *(const float4*)(s + i);
    v.x = f2tf(v.x); v.y = f2tf(v.y); v.z = f2tf(v.z); v.w = f2tf(v.w);
    *(float4*)(d + (size_t)w*DIM*DIM + i) = v;
}

// ---------------- LayerNorm (outputs pre-rounded to tf32) ----------------
__global__ __launch_bounds__(256) void ln_kernel(
    const float* __restrict__ feat, const float* __restrict__ lat,
    const float* __restrict__ mw, const float* __restrict__ mb,
    const float* __restrict__ lw, const float* __restrict__ lb)
{
    const int row = blockIdx.x;
    const int b = row / (FEAT+NQ);
    const int i = row - b*(FEAT+NQ);
    const float *src, *w, *bias;
    if (i < FEAT){ src = feat + (size_t)(b*FEAT + i)*DIM; w = mw; bias = mb; }
    else         { src = lat  + (size_t)(b*NQ + (i-FEAT))*DIM; w = lw; bias = lb; }

    const int tid = threadIdx.x;
    float4 x = ((const float4*)src)[tid];
    float s  = x.x + x.y + x.z + x.w;
    float sq = x.x*x.x + x.y*x.y + x.z*x.z + x.w*x.w;

    __shared__ float red[16];
    #pragma unroll
    for (int o = 16; o > 0; o >>= 1){
        s  += __shfl_xor_sync(0xffffffffu, s, o);
        sq += __shfl_xor_sync(0xffffffffu, sq, o);
    }
    const int wid = tid >> 5, lane = tid & 31;
    if (lane == 0){ red[wid] = s; red[8+wid] = sq; }
    __syncthreads();
    if (wid == 0){
        float ts = (lane < 8) ? red[lane]   : 0.f;
        float tq = (lane < 8) ? red[8+lane] : 0.f;
        #pragma unroll
        for (int o = 4; o > 0; o >>= 1){
            ts += __shfl_xor_sync(0xffffffffu, ts, o);
            tq += __shfl_xor_sync(0xffffffffu, tq, o);
        }
        if (lane == 0){ red[0] = ts; red[1] = tq; }
    }
    __syncthreads();
    const float mu   = red[0] * (1.f/DIM);
    const float var  = red[1] * (1.f/DIM) - mu*mu;
    const float rstd = rsqrtf(var + 1e-5f);

    float4 wv = ((const float4*)w)[tid];
    float4 bv = ((const float4*)bias)[tid];
    float4 y;
    y.x = f2tf((x.x - mu)*rstd*wv.x + bv.x);
    y.y = f2tf((x.y - mu)*rstd*wv.y + bv.y);
    y.z = f2tf((x.z - mu)*rstd*wv.z + bv.z);
    y.w = f2tf((x.w - mu)*rstd*wv.w + bv.w);
    ((float4*)(g_kv + (size_t)row*DIM))[tid] = y;
}

// ---------------- fused K+V GEMM: Ck = A@Bk, Cv = A@Bv ----------------
// 128x128 CTA tile, k-tile 32, 3-stage cp.async pipeline, 8 warps = 2(M)x4(N).
__global__ __launch_bounds__(256) void gemm_kv(
    const float* __restrict__ A,
    const float* __restrict__ Bk, const float* __restrict__ Bv,
    float* __restrict__ Ck, float* __restrict__ Cv)
{
    extern __shared__ float sm[];
    const int tid = threadIdx.x, lane = tid & 31, wid = tid >> 5;
    const int wm = wid & 1, wn = wid >> 1;
    const int g = lane >> 2, tg = lane & 3;
    const int row0 = blockIdx.y * 128, col0 = blockIdx.x * 128;

    const uint32_t sbase = smem_u32(sm);

    const int ar = tid >> 3, ac = tid & 7;
    const float* asrc[4];
    uint32_t adst[4];
    #pragma unroll
    for (int p = 0; p < 4; ++p){
        int r = p*32 + ar;
        asrc[p] = A + (size_t)(row0 + r)*DIM + ac*4;
        adst[p] = sbase + (uint32_t)(r*APAD + ac*4)*4u;
    }
    const int bk = tid >> 5, bc = tid & 31;
    const float* bksrc0 = Bk + (size_t)bk*DIM + col0 + bc*4;
    const float* bvsrc0 = Bv + (size_t)bk*DIM + col0 + bc*4;
    const uint32_t bkdst0 = sbase + (uint32_t)(128*APAD + bk*BPAD + bc*4)*4u;
    const uint32_t bvdst0 = bkdst0 + (uint32_t)(KT*BPAD)*4u;

    float ak_[4][4][4], av_[4][4][4];
    #pragma unroll
    for (int mi = 0; mi < 4; ++mi)
      #pragma unroll
      for (int ni = 0; ni < 4; ++ni)
        #pragma unroll
        for (int r = 0; r < 4; ++r){ ak_[mi][ni][r] = 0.f; av_[mi][ni][r] = 0.f; }

    #pragma unroll
    for (int pre = 0; pre < 2; ++pre){
        const uint32_t so = (uint32_t)pre*STGKV_F*4u;
        #pragma unroll
        for (int p = 0; p < 4; ++p) cpasync16(adst[p]+so, asrc[p] + pre*KT);
        #pragma unroll
        for (int p = 0; p < 4; ++p){
            cpasync16(bkdst0+so + (uint32_t)(p*8*BPAD)*4u, bksrc0 + (size_t)(pre*KT + p*8)*DIM);
            cpasync16(bvdst0+so + (uint32_t)(p*8*BPAD)*4u, bvsrc0 + (size_t)(pre*KT + p*8)*DIM);
        }
        cp_commit();
    }

    for (int kt = 0; kt < NKT; ++kt){
        const int slot = kt % NSTAGE;
        cp_wait1();
        __syncthreads();

        if (kt + 2 < NKT){
            const int ns = (kt+2) % NSTAGE;
            const uint32_t so = (uint32_t)ns*STGKV_F*4u;
            #pragma unroll
            for (int p = 0; p < 4; ++p) cpasync16(adst[p]+so, asrc[p] + (kt+2)*KT);
            #pragma unroll
            for (int p = 0; p < 4; ++p){
                cpasync16(bkdst0+so + (uint32_t)(p*8*BPAD)*4u, bksrc0 + (size_t)((kt+2)*KT + p*8)*DIM);
                cpasync16(bvdst0+so + (uint32_t)(p*8*BPAD)*4u, bvsrc0 + (size_t)((kt+2)*KT + p*8)*DIM);
            }
        }
        cp_commit();

        const float* as  = sm + (size_t)slot*STGKV_F;
        const float* bks = as + 128*APAD;
        const float* bvs = bks + KT*BPAD;
        #pragma unroll
        for (int ks = 0; ks < 4; ++ks){
            const int k0 = ks*8;
            unsigned a[4][4], bfk[4][2], bfv[4][2];
            #pragma unroll
            for (int mi = 0; mi < 4; ++mi){
                const float* ap = as + (wm*64 + mi*16 + g)*APAD + k0 + tg;
                a[mi][0] = __float_as_uint(ap[0]);
                a[mi][1] = __float_as_uint(ap[8*APAD]);
                a[mi][2] = __float_as_uint(ap[4]);
                a[mi][3] = __float_as_uint(ap[8*APAD+4]);
            }
            #pragma unroll
            for (int ni = 0; ni < 4; ++ni){
                const float* bp = bks + (k0+tg)*BPAD + wn*32 + ni*8 + g;
                bfk[ni][0] = __float_as_uint(bp[0]);
                bfk[ni][1] = __float_as_uint(bp[4*BPAD]);
                const float* vp = bvs + (k0+tg)*BPAD + wn*32 + ni*8 + g;
                bfv[ni][0] = __float_as_uint(vp[0]);
                bfv[ni][1] = __float_as_uint(vp[4*BPAD]);
            }
            #pragma unroll
            for (int mi = 0; mi < 4; ++mi)
              #pragma unroll
              for (int ni = 0; ni < 4; ++ni){
                mma8(ak_[mi][ni], a[mi], bfk[ni]);
                mma8(av_[mi][ni], a[mi], bfv[ni]);
              }
        }
    }

    #pragma unroll
    for (int mi = 0; mi < 4; ++mi){
        #pragma unroll
        for (int r2 = 0; r2 < 2; ++r2){
            const int row = row0 + wm*64 + mi*16 + r2*8 + g;
            float* ckp = Ck + (size_t)row*DIM + col0 + wn*32 + tg*2;
            float* cvp = Cv + (size_t)row*DIM + col0 + wn*32 + tg*2;
            #pragma unroll
            for (int ni = 0; ni < 4; ++ni){
                float2 vk; vk.x = ak_[mi][ni][r2*2]; vk.y = ak_[mi][ni][r2*2+1];
                *(float2*)(ckp + ni*8) = vk;
                float2 vv; vv.x = av_[mi][ni][r2*2]; vv.y = av_[mi][ni][r2*2+1];
                *(float2*)(cvp + ni*8) = vv;
            }
        }
    }
}

// ---------------- pipelined tf32 GEMM (single B; for Q and O projections) ----------------
__global__ __launch_bounds__(256) void gemm_mma(
    const float* __restrict__ A, const float* __restrict__ B,
    float* __restrict__ C, int qmode, float alpha)
{
    extern __shared__ float sm[];
    const int tid = threadIdx.x, lane = tid & 31, wid = tid >> 5;
    const int wm = wid & 1, wn = wid >> 1;
    const int g = lane >> 2, tg = lane & 3;
    const int row0 = blockIdx.y * 128, col0 = blockIdx.x * 128;

    const uint32_t sbase = smem_u32(sm);

    const int ar = tid >> 3, ac = tid & 7;
    const float* asrc[4];
    uint32_t adst[4];
    #pragma unroll
    for (int p = 0; p < 4; ++p){
        int r = p*32 + ar;
        int grow = row0 + r;
        if (qmode) grow = (grow >> 6)*(FEAT+NQ) + FEAT + (grow & 63);
        asrc[p] = A + (size_t)grow*DIM + ac*4;
        adst[p] = sbase + (uint32_t)(r*APAD + ac*4)*4u;
    }
    const int bk = tid >> 5, bc = tid & 31;
    const float* bsrc0 = B + (size_t)bk*DIM + col0 + bc*4;
    const uint32_t bdst0 = sbase + (uint32_t)(128*APAD + bk*BPAD + bc*4)*4u;

    float acc[4][4][4];
    #pragma unroll
    for (int mi = 0; mi < 4; ++mi)
      #pragma unroll
      for (int ni = 0; ni < 4; ++ni)
        #pragma unroll
        for (int r = 0; r < 4; ++r) acc[mi][ni][r] = 0.f;

    #pragma unroll
    for (int pre = 0; pre < 2; ++pre){
        const uint32_t so = (uint32_t)pre*STG_F*4u;
        #pragma unroll
        for (int p = 0; p < 4; ++p) cpasync16(adst[p]+so, asrc[p] + pre*KT);
        #pragma unroll
        for (int p = 0; p < 4; ++p) cpasync16(bdst0+so + (uint32_t)(p*8*BPAD)*4u,
                                              bsrc0 + (size_t)(pre*KT + p*8)*DIM);
        cp_commit();
    }

    for (int kt = 0; kt < NKT; ++kt){
        const int slot = kt % NSTAGE;
        cp_wait1();
        __syncthreads();

        if (kt + 2 < NKT){
            const int ns = (kt+2) % NSTAGE;
            const uint32_t so = (uint32_t)ns*STG_F*4u;
            #pragma unroll
            for (int p = 0; p < 4; ++p) cpasync16(adst[p]+so, asrc[p] + (kt+2)*KT);
            #pragma unroll
            for (int p = 0; p < 4; ++p) cpasync16(bdst0+so + (uint32_t)(p*8*BPAD)*4u,
                                                  bsrc0 + (size_t)((kt+2)*KT + p*8)*DIM);
        }
        cp_commit();

        const float* as = sm + (size_t)slot*STG_F;
        const float* bs = as + 128*APAD;
        #pragma unroll
        for (int ks = 0; ks < 4; ++ks){
            const int k0 = ks*8;
            unsigned a[4][4], bf[4][2];
            #pragma unroll
            for (int mi = 0; mi < 4; ++mi){
                const float* ap = as + (wm*64 + mi*16 + g)*APAD + k0 + tg;
                a[mi][0] = __float_as_uint(ap[0]);
                a[mi][1] = __float_as_uint(ap[8*APAD]);
                a[mi][2] = __float_as_uint(ap[4]);
                a[mi][3] = __float_as_uint(ap[8*APAD+4]);
            }
            #pragma unroll
            for (int ni = 0; ni < 4; ++ni){
                const float* bp = bs + (k0+tg)*BPAD + wn*32 + ni*8 + g;
                bf[ni][0] = __float_as_uint(bp[0]);
                bf[ni][1] = __float_as_uint(bp[4*BPAD]);
            }
            #pragma unroll
            for (int mi = 0; mi < 4; ++mi)
              #pragma unroll
              for (int ni = 0; ni < 4; ++ni)
                mma8(acc[mi][ni], a[mi], bf[ni]);
        }
    }

    #pragma unroll
    for (int mi = 0; mi < 4; ++mi){
        #pragma unroll
        for (int r2 = 0; r2 < 2; ++r2){
            const int row = row0 + wm*64 + mi*16 + r2*8 + g;
            float* cp = C + (size_t)row*DIM + col0 + wn*32 + tg*2;
            #pragma unroll
            for (int ni = 0; ni < 4; ++ni){
                float2 v;
                v.x = alpha*acc[mi][ni][r2*2];
                v.y = alpha*acc[mi][ni][r2*2+1];
                *(float2*)(cp + ni*8) = v;
            }
        }
    }
}

// ---------------- split-KV flash attention: block (h, b, split) ----------------
// Emits unnormalized O numerator + per-row (m, l); combine kernel merges splits.
__global__ __launch_bounds__(256) void attn_kernel(const int* __restrict__ mask)
{
    __shared__ float Ks[64][68];
    __shared__ float Vs[64][68];
    __shared__ float madd[64];
    __shared__ float alpha_s[64], m_s[64], l_s[64];

    const int h = blockIdx.x, b = blockIdx.y, sp = blockIdx.z;
    const int cbeg = sp ? SPLIT_MID : 0;
    const int cend = sp ? 65 : SPLIT_MID;
    const int tid = threadIdx.x, lane = tid & 31, wid = tid >> 5;
    const int wm = wid & 3, wn = wid >> 2;
    const int g = lane >> 2, tg = lane & 3;

    unsigned qf[8][4];
    {
        const float* qp = g_q + (size_t)(b*NQ + wm*16)*DIM + h*64;
        #pragma unroll
        for (int ks = 0; ks < 8; ++ks){
            qf[ks][0] = f2t(qp[(size_t)(g  )*DIM + ks*8+tg  ]);
            qf[ks][1] = f2t(qp[(size_t)(g+8)*DIM + ks*8+tg  ]);
            qf[ks][2] = f2t(qp[(size_t)(g  )*DIM + ks*8+tg+4]);
            qf[ks][3] = f2t(qp[(size_t)(g+8)*DIM + ks*8+tg+4]);
        }
    }
    float o[4][4];
    #pragma unroll
    for (int ni = 0; ni < 4; ++ni)
      #pragma unroll
      for (int r = 0; r < 4; ++r) o[ni][r] = 0.f;

    if (tid < 64){ m_s[tid] = -1e30f; l_s[tid] = 0.f; }
    __syncthreads();

    for (int c = cbeg; c < cend; ++c){
        const size_t rbase = (size_t)(b*(FEAT+NQ) + c*64);
        #pragma unroll
        for (int i = 0; i < 4; ++i){
            int idx = tid + i*256;
            int r = idx >> 4, c4 = (idx & 15) << 2;
            const float4 kk = *(const float4*)(g_k + (rbase+r)*DIM + h*64 + c4);
            Ks[r][c4+0]=f2tf(kk.x); Ks[r][c4+1]=f2tf(kk.y); Ks[r][c4+2]=f2tf(kk.z); Ks[r][c4+3]=f2tf(kk.w);
            const float4 vv = *(const float4*)(g_v + (rbase+r)*DIM + h*64 + c4);
            Vs[r][c4+0]=f2tf(vv.x); Vs[r][c4+1]=f2tf(vv.y); Vs[r][c4+2]=f2tf(vv.z); Vs[r][c4+3]=f2tf(vv.w);
        }
        if (tid < 64)
            madd[tid] = (c < 64) ? (mask[b*FEAT + c*64 + tid] ? 0.f : -1e30f) : 0.f;
        __syncthreads();

        float s[4][4];
        #pragma unroll
        for (int ni = 0; ni < 4; ++ni)
          #pragma unroll
          for (int r = 0; r < 4; ++r) s[ni][r] = 0.f;
        #pragma unroll
        for (int ks = 0; ks < 8; ++ks){
            unsigned bf[4][2];
            #pragma unroll
            for (int ni = 0; ni < 4; ++ni){
                int n = wn*32 + ni*8 + g;
                bf[ni][0] = __float_as_uint(Ks[n][ks*8+tg  ]);
                bf[ni][1] = __float_as_uint(Ks[n][ks*8+tg+4]);
            }
            #pragma unroll
            for (int ni = 0; ni < 4; ++ni) mma8(s[ni], qf[ks], bf[ni]);
        }
        __syncthreads();

        {
            const int r0 = wm*16 + g;
            #pragma unroll
            for (int ni = 0; ni < 4; ++ni){
                int cc = wn*32 + ni*8 + tg*2;
                Ks[r0  ][cc]   = s[ni][0] + madd[cc];
                Ks[r0  ][cc+1] = s[ni][1] + madd[cc+1];
                Ks[r0+8][cc]   = s[ni][2] + madd[cc];
                Ks[r0+8][cc+1] = s[ni][3] + madd[cc+1];
            }
        }
        __syncthreads();

        {
            const int q = tid >> 2, part = tid & 3;
            float pm = -1e30f;
            #pragma unroll
            for (int j = 0; j < 16; ++j) pm = fmaxf(pm, Ks[q][part*16+j]);
            pm = fmaxf(pm, __shfl_xor_sync(0xffffffffu, pm, 1));
            pm = fmaxf(pm, __shfl_xor_sync(0xffffffffu, pm, 2));
            const float mold = m_s[q];
            const float mnew = fmaxf(mold, pm);
            float psum = 0.f;
            #pragma unroll
            for (int j = 0; j < 16; ++j){
                float sv = Ks[q][part*16+j];
                float p  = (sv > -1e29f) ? __expf(sv - mnew) : 0.f;
                Ks[q][part*16+j] = f2tf(p);
                psum += p;
            }
            psum += __shfl_xor_sync(0xffffffffu, psum, 1);
            psum += __shfl_xor_sync(0xffffffffu, psum, 2);
            if (part == 0){
                float al = __expf(mold - mnew);
                alpha_s[q] = al;
                m_s[q]     = mnew;
                l_s[q]     = l_s[q]*al + psum;
            }
        }
        __syncthreads();

        {
            const float al0 = alpha_s[wm*16 + g];
            const float al1 = alpha_s[wm*16 + 8 + g];
            #pragma unroll
            for (int ni = 0; ni < 4; ++ni){
                o[ni][0]*=al0; o[ni][1]*=al0; o[ni][2]*=al1; o[ni][3]*=al1;
            }
            #pragma unroll
            for (int ks = 0; ks < 8; ++ks){
                unsigned pa[4];
                const int r0 = wm*16;
                pa[0] = __float_as_uint(Ks[r0+g  ][ks*8+tg  ]);
                pa[1] = __float_as_uint(Ks[r0+8+g][ks*8+tg  ]);
                pa[2] = __float_as_uint(Ks[r0+g  ][ks*8+tg+4]);
                pa[3] = __float_as_uint(Ks[r0+8+g][ks*8+tg+4]);
                unsigned bf[4][2];
                #pragma unroll
                for (int ni = 0; ni < 4; ++ni){
                    int n = wn*32 + ni*8 + g;
                    bf[ni][0] = __float_as_uint(Vs[ks*8+tg  ][n]);
                    bf[ni][1] = __float_as_uint(Vs[ks*8+tg+4][n]);
                }
                #pragma unroll
                for (int ni = 0; ni < 4; ++ni) mma8(o[ni], pa, bf[ni]);
            }
        }
        __syncthreads();
    }

    // epilogue: write unnormalized numerator + (m,l)
    {
        float* gpo = g_po + (size_t)sp*LROWS*DIM;
        const int r0 = b*NQ + wm*16 + g;
        #pragma unroll
        for (int ni = 0; ni < 4; ++ni){
            int cc = h*64 + wn*32 + ni*8 + tg*2;
            gpo[(size_t)r0*DIM + cc]       = o[ni][0];
            gpo[(size_t)r0*DIM + cc+1]     = o[ni][1];
            gpo[(size_t)(r0+8)*DIM + cc]   = o[ni][2];
            gpo[(size_t)(r0+8)*DIM + cc+1] = o[ni][3];
        }
        if (tid < 64){
            const int off = sp*MLSZ + (b*16 + h)*64 + tid;
            g_sm[off] = m_s[tid];
            g_sl[off] = l_s[tid];
        }
    }
}

// ---------------- combine splits -> g_at (tf32-rounded) ----------------
__global__ __launch_bounds__(256) void combine_kernel(float* __restrict__ dst)
{
    const int r = blockIdx.x;                 // 0..LROWS-1
    const int b = r >> 6, q = r & 63;
    const int tid = threadIdx.x;
    const int h = tid >> 4;                   // 4 floats/thread -> head = tid/16
    const int idx = (b*16 + h)*64 + q;

    const float m0 = g_sm[idx],        m1 = g_sm[MLSZ + idx];
    const float l0 = g_sl[idx],        l1 = g_sl[MLSZ + idx];
    const float mm = fmaxf(m0, m1);
    const float w0 = __expf(m0 - mm), w1 = __expf(m1 - mm);
    const float inv = 1.f / (w0*l0 + w1*l1);

    const float4 a = *(const float4*)(g_po + (size_t)r*DIM + tid*4);
    const float4 c = *(const float4*)(g_po + (size_t)LROWS*DIM + (size_t)r*DIM + tid*4);
    float4 o;
    o.x = f2tf((w0*a.x + w1*c.x)*inv);
    o.y = f2tf((w0*a.y + w1*c.y)*inv);
    o.z = f2tf((w0*a.z + w1*c.z)*inv);
    o.w = f2tf((w0*a.w + w1*c.w)*inv);
    *(float4*)(dst + (size_t)r*DIM + tid*4) = o;
}

// ---------------- launch ----------------
extern "C" void kernel_launch(void* const* d_in, const int* in_sizes, int n_in,
                              void* d_out, int out_size)
{
    const float* feat = (const float*)d_in[0];
    const float* lat  = (const float*)d_in[1];
    const int*   msk  = (const int*)  d_in[2];
    const float* mw   = (const float*)d_in[3];
    const float* mb   = (const float*)d_in[4];
    const float* lw   = (const float*)d_in[5];
    const float* lb   = (const float*)d_in[6];
    const float* Wq   = (const float*)d_in[7];
    const float* Wk   = (const float*)d_in[8];
    const float* Wv   = (const float*)d_in[9];
    const float* Wo   = (const float*)d_in[10];
    float* out = (float*)d_out;

    float *p_kv, *p_k, *p_v, *p_q, *p_at, *p_w;
    cudaGetSymbolAddress((void**)&p_kv, g_kv);
    cudaGetSymbolAddress((void**)&p_k,  g_k);
    cudaGetSymbolAddress((void**)&p_v,  g_v);
    cudaGetSymbolAddress((void**)&p_q,  g_q);
    cudaGetSymbolAddress((void**)&p_at, g_at);
    cudaGetSymbolAddress((void**)&p_w,  g_w);

    cudaFuncSetAttribute(gemm_mma, cudaFuncAttributeMaxDynamicSharedMemorySize, GEMM_SMEM);
    cudaFuncSetAttribute(gemm_kv,  cudaFuncAttributeMaxDynamicSharedMemorySize, GEMMKV_SMEM);

    round_all<<<4096, 256>>>(Wk, Wv, Wq, Wo, p_w);
    ln_kernel<<<KVR, 256>>>(feat, lat, mw, mb, lw, lb);

    dim3 gbig(8, KVR/128);          // x-fastest: 8 n-blocks share A tiles via L2
    gemm_kv<<<gbig, 256, GEMMKV_SMEM>>>(p_kv,
        p_w + 0*(size_t)DIM*DIM, p_w + 1*(size_t)DIM*DIM, p_k, p_v);

    dim3 gsmall(8, LROWS/128);
    gemm_mma<<<gsmall, 256, GEMM_SMEM>>>(p_kv, p_w + 2*(size_t)DIM*DIM, p_q, 1, 0.125f);

    dim3 gattn(16, NB, NSPLIT);
    attn_kernel<<<gattn, 256>>>(msk);
    combine_kernel<<<LROWS, 256>>>(p_at);

    gemm_mma<<<gsmall, 256, GEMM_SMEM>>>(p_at, p_w + 3*(size_t)DIM*DIM, out, 0, 1.0f);
}